// round 3
// baseline (speedup 1.0000x reference)
#include <cuda_runtime.h>
#include <cstdint>

#define HH 56
#define WW 56
#define HM 50
#define WM 50
#define NPLANES 16384            // 64 * 256
#define COUNT_M 51380224ull      // 64*256*56*56

// Scratch (allocation-free per harness rules)
__device__ unsigned long long g_ones;
__device__ float g_scale;
__device__ unsigned long long g_dmask[NPLANES * HH];   // 7.34 MB: dilated mask, 1 u64 row / output row

__global__ void k_zero() { g_ones = 0ull; }

// One CTA per (b,c) plane: build seed bitmask rows, separable 7x7 bit-dilation,
// popcount + store packed dilated mask.
__global__ __launch_bounds__(128) void k_pass1(const float* __restrict__ u,
                                               const float* __restrict__ gamma) {
    __shared__ unsigned long long srow[HM];
    __shared__ unsigned long long hrow[HM];
    __shared__ unsigned wsum[4];
    const int plane = blockIdx.x;
    const int tid = threadIdx.x;
    const float g = __ldg(gamma);

    if (tid < HM) srow[tid] = 0ull;
    __syncthreads();

    // u plane: 50*50 = 2500 floats = 625 float4 (plane stride 10000 B, 16B aligned)
    const float4* u4 = (const float4*)(u + (size_t)plane * (HM * WM));
    for (int i = tid; i < (HM * WM) / 4; i += 128) {
        float4 v = u4[i];
        int e = i * 4;
        if (v.x < g) atomicOr(&srow[ e      / WM], 1ull << ( e      % WM));
        if (v.y < g) atomicOr(&srow[(e + 1) / WM], 1ull << ((e + 1) % WM));
        if (v.z < g) atomicOr(&srow[(e + 2) / WM], 1ull << ((e + 2) % WM));
        if (v.w < g) atomicOr(&srow[(e + 3) / WM], 1ull << ((e + 3) % WM));
    }
    __syncthreads();

    // Horizontal dilation: output bit o = OR of seed bits [o-6, o]  (shifts 0..6)
    if (tid < HM) {
        unsigned long long m  = srow[tid];
        unsigned long long t1 = m  | (m  << 1);
        unsigned long long t2 = t1 | (t1 << 2);
        hrow[tid] = t2 | (t2 << 3);        // covers shifts 0..6, bits fit in [0,55]
    }
    __syncthreads();

    // Vertical dilation: output row o = OR of hrows [o-6, o] clipped to [0, 49]
    unsigned v = 0;
    if (tid < HH) {
        int lo = tid - 6; if (lo < 0) lo = 0;
        int hi = (tid < HM) ? tid : (HM - 1);
        unsigned long long d = 0ull;
        #pragma unroll 1
        for (int r = lo; r <= hi; ++r) d |= hrow[r];
        g_dmask[(size_t)plane * HH + tid] = d;
        v = (unsigned)__popcll(d);
    }
    // block reduce dilated-ones, one RED per CTA
    #pragma unroll
    for (int off = 16; off; off >>= 1) v += __shfl_down_sync(0xffffffffu, v, off);
    if ((tid & 31) == 0) wsum[tid >> 5] = v;
    __syncthreads();
    if (tid == 0)
        atomicAdd(&g_ones, (unsigned long long)(wsum[0] + wsum[1] + wsum[2] + wsum[3]));
}

__global__ void k_finalize() {
    unsigned long long ones = g_ones;
    g_scale = (float)((double)COUNT_M / (double)(COUNT_M - ones));
}

// Elementwise apply: out = bit ? 0 : x * scale, float4 per thread.
__global__ __launch_bounds__(256) void k_pass2(const float* __restrict__ x,
                                               float* __restrict__ out) {
    const unsigned i4 = blockIdx.x * 256u + threadIdx.x;   // float4 index, < 12,845,056
    const float s = g_scale;
    const unsigned plane = i4 / 784u;                      // 784 float4 per 56x56 plane
    const unsigned rem   = i4 - plane * 784u;
    const unsigned row   = rem / 14u;                      // 14 float4 per row
    const unsigned w4    = rem - row * 14u;
    const unsigned long long d = __ldg(&g_dmask[plane * HH + row]);
    const float4 xv = __ldg(((const float4*)x) + i4);
    const unsigned nib = (unsigned)(d >> (w4 * 4u)) & 0xFu;
    float4 o;
    o.x = (nib & 1u) ? 0.f : xv.x * s;
    o.y = (nib & 2u) ? 0.f : xv.y * s;
    o.z = (nib & 4u) ? 0.f : xv.z * s;
    o.w = (nib & 8u) ? 0.f : xv.w * s;
    ((float4*)out)[i4] = o;
}

extern "C" void kernel_launch(void* const* d_in, const int* in_sizes, int n_in,
                              void* d_out, int out_size) {
    const float* x     = (const float*)d_in[0];
    const float* u     = (const float*)d_in[1];
    const float* gamma = (const float*)d_in[2];
    float* out = (float*)d_out;

    k_zero<<<1, 1>>>();
    k_pass1<<<NPLANES, 128>>>(u, gamma);
    k_finalize<<<1, 1>>>();
    k_pass2<<<(unsigned)(COUNT_M / 4ull / 256ull), 256>>>(x, out);   // 50176 blocks, exact
}